// round 5
// baseline (speedup 1.0000x reference)
#include <cuda_runtime.h>
#include <cstdint>
#include <cstddef>

#define NU 100000
#define NI 200000
#define BB 3
#define EE 1000000
#define DD 64

// Scratch accumulators (device globals: allocation-free per harness rules)
__device__ float g_uscr[(size_t)BB * NU * DD];   // 76.8 MB
__device__ float g_iscr[(size_t)BB * NI * DD];   // 153.6 MB

// ---------------------------------------------------------------------------
// Scatter: COO spmm  out[row] += val * dense[col]  (red.global.add.v4.f32)
// Persistent grid-stride version: with grid 3907 it sweeps once (== R1 kernel,
// measured 46.9us); with grid 444 (3 CTAs/SM) it loops and leaves regs/smem
// for a concurrent gemm_sig (2 CTAs/SM co-resident).
// ---------------------------------------------------------------------------
__global__ void __launch_bounds__(256) scatter_kernel(
    const float* __restrict__ vals,
    const int*   __restrict__ rows,
    const int*   __restrict__ cols,
    const float* __restrict__ dense,
    float*       __restrict__ out,
    int nE)
{
    int lane   = threadIdx.x & 31;
    int warpId = (blockIdx.x * blockDim.x + threadIdx.x) >> 5;
    int nWarps = (gridDim.x * blockDim.x) >> 5;
    int half   = lane >> 4;
    int l4     = lane & 15;

    for (int base = warpId * 32; base < nE; base += nWarps * 32) {
        int e = base + lane;
        float v = 0.0f; int r = 0, c = 0;
        if (e < nE) { v = vals[e]; r = rows[e]; c = cols[e]; }   // tail: v=0 -> +0

        #pragma unroll
        for (int i = 0; i < 16; i++) {
            int src = 2 * i + half;
            float vv = __shfl_sync(0xffffffffu, v, src);
            int   rr = __shfl_sync(0xffffffffu, r, src);
            int   cc = __shfl_sync(0xffffffffu, c, src);

            const float4* dp = reinterpret_cast<const float4*>(dense + (size_t)cc * DD) + l4;
            float4 d = __ldg(dp);
            float4 p;
            p.x = vv * d.x; p.y = vv * d.y; p.z = vv * d.z; p.w = vv * d.w;

            float* op = out + (size_t)rr * DD + (size_t)l4 * 4;
            asm volatile("red.global.add.v4.f32 [%0], {%1,%2,%3,%4};"
                         :: "l"(op), "f"(p.x), "f"(p.y), "f"(p.z), "f"(p.w)
                         : "memory");
        }
    }
}

// ---------------------------------------------------------------------------
// GEMM + sigmoid + in-tile mean (R1 scalar version; issue=76.8% solo).
// ---------------------------------------------------------------------------
__device__ __forceinline__ float sigmoidf_(float x) {
    return 1.0f / (1.0f + __expf(-x));
}

#define F4_GET(v, kk) ((kk) == 0 ? (v).x : ((kk) == 1 ? (v).y : ((kk) == 2 ? (v).z : (v).w)))

__global__ void __launch_bounds__(256) gemm_sig(
    const float* __restrict__ scr,      // [3, N, 64]
    const float* __restrict__ W,        // [64, 64] row-major (k, col)
    float*       __restrict__ out_per,  // [3, N, 64]
    float*       __restrict__ out_mean, // [N, 64]
    int N)
{
    __shared__ float4 sX[3 * 32 * 16];  // 24 KB
    __shared__ float  sW[64 * 64];      // 16 KB

    int t  = threadIdx.x;
    int n0 = blockIdx.x * 32;

    const float4* scr4 = reinterpret_cast<const float4*>(scr);
    #pragma unroll
    for (int i = 0; i < 6; i++) {
        int u  = t + i * 256;
        int rb = u >> 4;
        int kq = u & 15;
        int b  = rb >> 5;
        int r  = rb & 31;
        sX[u] = scr4[((size_t)b * N + n0 + r) * 16 + kq];
    }
    const float4* W4  = reinterpret_cast<const float4*>(W);
    float4*       sW4 = reinterpret_cast<float4*>(sW);
    #pragma unroll
    for (int i = 0; i < 4; i++) sW4[t + i * 256] = W4[t + i * 256];
    __syncthreads();

    int c = t & 31;
    int g = t >> 5;

    float acc[3][4][2];
    #pragma unroll
    for (int b = 0; b < 3; b++)
        #pragma unroll
        for (int i = 0; i < 4; i++) { acc[b][i][0] = 0.0f; acc[b][i][1] = 0.0f; }

    for (int k4 = 0; k4 < 16; k4++) {
        float4 xv[3][4];
        #pragma unroll
        for (int b = 0; b < 3; b++)
            #pragma unroll
            for (int i = 0; i < 4; i++)
                xv[b][i] = sX[(b * 32 + g + 8 * i) * 16 + k4];

        #pragma unroll
        for (int kk = 0; kk < 4; kk++) {
            int k = k4 * 4 + kk;
            float w0 = sW[k * 64 + c];
            float w1 = sW[k * 64 + c + 32];
            #pragma unroll
            for (int b = 0; b < 3; b++)
                #pragma unroll
                for (int i = 0; i < 4; i++) {
                    float xk = F4_GET(xv[b][i], kk);
                    acc[b][i][0] = fmaf(xk, w0, acc[b][i][0]);
                    acc[b][i][1] = fmaf(xk, w1, acc[b][i][1]);
                }
        }
    }

    #pragma unroll
    for (int i = 0; i < 4; i++) {
        int row = n0 + g + 8 * i;
        #pragma unroll
        for (int c2 = 0; c2 < 2; c2++) {
            int col = c + 32 * c2;
            float m = 0.0f;
            #pragma unroll
            for (int b = 0; b < 3; b++) {
                float y = acc[b][i][c2];
                m += y;
                out_per[((size_t)b * N + row) * 64 + col] = sigmoidf_(y);
            }
            out_mean[(size_t)row * 64 + col] = sigmoidf_(m * (1.0f / 3.0f));
        }
    }
}

// ---------------------------------------------------------------------------
// Lazy stream/event creation (first call = correctness run, outside capture).
// ---------------------------------------------------------------------------
static cudaStream_t side_stream() {
    static cudaStream_t s = nullptr;
    if (!s) cudaStreamCreateWithFlags(&s, cudaStreamNonBlocking);
    return s;
}
static cudaEvent_t ev(int i) {
    static cudaEvent_t e[4] = {nullptr, nullptr, nullptr, nullptr};
    if (!e[i]) cudaEventCreateWithFlags(&e[i], cudaEventDisableTiming);
    return e[i];
}

// ---------------------------------------------------------------------------
// Launch DAG:
//   stream0: memset_i -> i2u x3 (full grid) -> u2i x3 (444 CTAs, throttled)
//            -> gemm_u -> join
//   s1:      memset_u -> (wait i2u) gemm_i   [co-resident with throttled u2i]
// ---------------------------------------------------------------------------
extern "C" void kernel_launch(void* const* d_in, const int* in_sizes, int n_in,
                              void* d_out, int out_size)
{
    const float* user_emb = (const float*)d_in[0];
    const float* item_emb = (const float*)d_in[1];
    const float* u2i_vals = (const float*)d_in[2];
    const int*   u2i_rows = (const int*)  d_in[3];
    const int*   u2i_cols = (const int*)  d_in[4];
    const float* i2u_vals = (const float*)d_in[5];
    const int*   i2u_rows = (const int*)  d_in[6];
    const int*   i2u_cols = (const int*)  d_in[7];
    const float* u_w      = (const float*)d_in[8];
    const float* i_w      = (const float*)d_in[9];

    float* out     = (float*)d_out;
    float* out_ue  = out;                                                 // [NU,64]
    float* out_ie  = out + (size_t)NU * DD;                               // [NI,64]
    float* out_ues = out + (size_t)(NU + NI) * DD;                        // [3,NU,64]
    float* out_ies = out + (size_t)(NU + NI) * DD + (size_t)BB * NU * DD; // [3,NI,64]

    void* p;
    cudaGetSymbolAddress(&p, g_uscr); float* uscr = (float*)p;
    cudaGetSymbolAddress(&p, g_iscr); float* iscr = (float*)p;

    cudaStream_t s1 = side_stream();
    cudaEvent_t e_fork = ev(0), e_mu = ev(1), e_i2u = ev(2), e_join = ev(3);

    cudaEventRecord(e_fork, 0);
    cudaStreamWaitEvent(s1, e_fork, 0);

    // s1: zero user scratch (parallel with memset_i / i2u)
    cudaMemsetAsync(uscr, 0, sizeof(g_uscr), s1);
    cudaEventRecord(e_mu, s1);

    // stream0: zero item scratch, then 3 i2u scatters at full grid (solo phase)
    cudaMemsetAsync(iscr, 0, sizeof(g_iscr), 0);

    const int FULL_GRID = (EE + 255) / 256;   // one sweep == R1 config
    const int THROTTLED = 444;                // 3 CTAs/SM -> room for 2 gemm CTAs/SM

    for (int b = 0; b < BB; b++) {
        scatter_kernel<<<FULL_GRID, 256>>>(
            i2u_vals + (size_t)b * EE, i2u_rows + (size_t)b * EE,
            i2u_cols + (size_t)b * EE, user_emb,
            iscr + (size_t)b * NI * DD, EE);
    }
    cudaEventRecord(e_i2u, 0);

    // s1: big GEMM on item scratch, genuinely concurrent with throttled u2i
    cudaStreamWaitEvent(s1, e_i2u, 0);
    gemm_sig<<<NI / 32, 256, 0, s1>>>(iscr, i_w, out_ies, out_ie, NI);
    cudaEventRecord(e_join, s1);

    // stream0: u2i scatters, resource-throttled persistent grid
    cudaStreamWaitEvent(0, e_mu, 0);
    for (int b = 0; b < BB; b++) {
        scatter_kernel<<<THROTTLED, 256>>>(
            u2i_vals + (size_t)b * EE, u2i_rows + (size_t)b * EE,
            u2i_cols + (size_t)b * EE, item_emb,
            uscr + (size_t)b * NU * DD, EE);
    }
    gemm_sig<<<NU / 32, 256>>>(uscr, u_w, out_ues, out_ue, NU);

    // join s1 back into the origin stream
    cudaStreamWaitEvent(0, e_join, 0);
}

// round 6
// speedup vs baseline: 1.0881x; 1.0881x over previous
#include <cuda_runtime.h>
#include <cstdint>
#include <cstddef>

#define NU 100000
#define NI 200000
#define BB 3
#define EE 1000000
#define DD 64

// Scratch accumulators (device globals: allocation-free per harness rules)
__device__ float g_uscr[(size_t)BB * NU * DD];   // 76.8 MB
__device__ float g_iscr[(size_t)BB * NI * DD];   // 153.6 MB

// ---------------------------------------------------------------------------
// Scatter: COO spmm  out[row] += val * dense[col]  (red.global.add.v4.f32)
// Grid-stride persistent; at FULL_GRID it sweeps once (R1 config, 46.9us).
// ---------------------------------------------------------------------------
__global__ void __launch_bounds__(256) scatter_kernel(
    const float* __restrict__ vals,
    const int*   __restrict__ rows,
    const int*   __restrict__ cols,
    const float* __restrict__ dense,
    float*       __restrict__ out,
    int nE)
{
    int lane   = threadIdx.x & 31;
    int warpId = (blockIdx.x * blockDim.x + threadIdx.x) >> 5;
    int nWarps = (gridDim.x * blockDim.x) >> 5;
    int half   = lane >> 4;
    int l4     = lane & 15;

    for (int base = warpId * 32; base < nE; base += nWarps * 32) {
        int e = base + lane;
        float v = 0.0f; int r = 0, c = 0;
        if (e < nE) { v = vals[e]; r = rows[e]; c = cols[e]; }

        #pragma unroll
        for (int i = 0; i < 16; i++) {
            int src = 2 * i + half;
            float vv = __shfl_sync(0xffffffffu, v, src);
            int   rr = __shfl_sync(0xffffffffu, r, src);
            int   cc = __shfl_sync(0xffffffffu, c, src);

            const float4* dp = reinterpret_cast<const float4*>(dense + (size_t)cc * DD) + l4;
            float4 d = __ldg(dp);
            float4 p;
            p.x = vv * d.x; p.y = vv * d.y; p.z = vv * d.z; p.w = vv * d.w;

            float* op = out + (size_t)rr * DD + (size_t)l4 * 4;
            asm volatile("red.global.add.v4.f32 [%0], {%1,%2,%3,%4};"
                         :: "l"(op), "f"(p.x), "f"(p.y), "f"(p.z), "f"(p.w)
                         : "memory");
        }
    }
}

// ---------------------------------------------------------------------------
// tf32 tensor-core GEMM + sigmoid + in-register behavior mean.
// Block: 64 rows x 64 cols x 3 behaviors; 8 warps (4 m-tiles x 2 n-halves).
// mma.sync.m16n8k8.tf32; W in smem (tf32, stride 72 -> conflict-free frags);
// A fragments loaded directly from global + cvt.rna.tf32.
// ---------------------------------------------------------------------------
__device__ __forceinline__ float sigmoidf_(float x) {
    return 1.0f / (1.0f + __expf(-x));
}
__device__ __forceinline__ uint32_t to_tf32(float x) {
    uint32_t v;
    asm("cvt.rna.tf32.f32 %0, %1;" : "=r"(v) : "f"(x));
    return v;
}
#define MMA_TF32(c0,c1,c2,c3, a0,a1,a2,a3, b0,b1)                            \
    asm volatile("mma.sync.aligned.m16n8k8.row.col.f32.tf32.tf32.f32 "       \
        "{%0,%1,%2,%3}, {%4,%5,%6,%7}, {%8,%9}, {%0,%1,%2,%3};"              \
        : "+f"(c0), "+f"(c1), "+f"(c2), "+f"(c3)                             \
        : "r"(a0), "r"(a1), "r"(a2), "r"(a3), "r"(b0), "r"(b1))

__global__ void __launch_bounds__(256) gemm_sig_mma(
    const float* __restrict__ scr,      // [3, N, 64]
    const float* __restrict__ W,        // [64, 64] row-major (k, n)
    float*       __restrict__ out_per,  // [3, N, 64]
    float*       __restrict__ out_mean, // [N, 64]
    int N)
{
    __shared__ uint32_t sW[64 * 72];    // tf32 bits, padded stride 72

    int t = threadIdx.x;
    #pragma unroll
    for (int i = 0; i < 16; i++) {
        int j = t + i * 256;            // 0..4095
        int k = j >> 6, n = j & 63;
        sW[k * 72 + n] = to_tf32(W[j]);
    }
    __syncthreads();

    int warp = t >> 5, lane = t & 31;
    int gid = lane >> 2, tig = lane & 3;
    int mt = warp & 3, nh = warp >> 2;

    int n0 = blockIdx.x * 64;
    int r0 = n0 + mt * 16 + gid;
    int r1 = r0 + 8;
    bool p0 = r0 < N, p1 = r1 < N;

    float acc[3][4][4];
    #pragma unroll
    for (int b = 0; b < 3; b++)
        #pragma unroll
        for (int nt = 0; nt < 4; nt++)
            #pragma unroll
            for (int q = 0; q < 4; q++) acc[b][nt][q] = 0.0f;

    #pragma unroll 2
    for (int ks = 0; ks < 8; ks++) {
        int k0 = ks * 8;
        uint32_t bf[4][2];
        #pragma unroll
        for (int nt = 0; nt < 4; nt++) {
            int col = nh * 32 + nt * 8 + gid;
            bf[nt][0] = sW[(k0 + tig) * 72 + col];
            bf[nt][1] = sW[(k0 + tig + 4) * 72 + col];
        }
        #pragma unroll
        for (int b = 0; b < 3; b++) {
            const float* xb = scr + (size_t)b * N * 64;
            float f0 = p0 ? __ldg(xb + (size_t)r0 * 64 + k0 + tig)     : 0.0f;
            float f2 = p0 ? __ldg(xb + (size_t)r0 * 64 + k0 + tig + 4) : 0.0f;
            float f1 = p1 ? __ldg(xb + (size_t)r1 * 64 + k0 + tig)     : 0.0f;
            float f3 = p1 ? __ldg(xb + (size_t)r1 * 64 + k0 + tig + 4) : 0.0f;
            uint32_t a0 = to_tf32(f0), a1 = to_tf32(f1);
            uint32_t a2 = to_tf32(f2), a3 = to_tf32(f3);
            #pragma unroll
            for (int nt = 0; nt < 4; nt++)
                MMA_TF32(acc[b][nt][0], acc[b][nt][1], acc[b][nt][2], acc[b][nt][3],
                         a0, a1, a2, a3, bf[nt][0], bf[nt][1]);
        }
    }

    // Epilogue: sigmoid per behavior + sigmoid(mean of pre-activations)
    const float third = 1.0f / 3.0f;
    #pragma unroll
    for (int nt = 0; nt < 4; nt++) {
        int c0 = nh * 32 + nt * 8 + 2 * tig;
        float m0 = 0.0f, m1 = 0.0f, m2 = 0.0f, m3 = 0.0f;
        #pragma unroll
        for (int b = 0; b < 3; b++) {
            float y0 = acc[b][nt][0], y1 = acc[b][nt][1];
            float y2 = acc[b][nt][2], y3 = acc[b][nt][3];
            m0 += y0; m1 += y1; m2 += y2; m3 += y3;
            if (p0) *reinterpret_cast<float2*>(out_per + ((size_t)b * N + r0) * 64 + c0)
                        = make_float2(sigmoidf_(y0), sigmoidf_(y1));
            if (p1) *reinterpret_cast<float2*>(out_per + ((size_t)b * N + r1) * 64 + c0)
                        = make_float2(sigmoidf_(y2), sigmoidf_(y3));
        }
        if (p0) *reinterpret_cast<float2*>(out_mean + (size_t)r0 * 64 + c0)
                    = make_float2(sigmoidf_(m0 * third), sigmoidf_(m1 * third));
        if (p1) *reinterpret_cast<float2*>(out_mean + (size_t)r1 * 64 + c0)
                    = make_float2(sigmoidf_(m2 * third), sigmoidf_(m3 * third));
    }
}

// ---------------------------------------------------------------------------
// Lazy stream/event creation (first call = correctness run, outside capture).
// ---------------------------------------------------------------------------
static cudaStream_t side_stream() {
    static cudaStream_t s = nullptr;
    if (!s) cudaStreamCreateWithFlags(&s, cudaStreamNonBlocking);
    return s;
}
static cudaEvent_t ev(int i) {
    static cudaEvent_t e[4] = {nullptr, nullptr, nullptr, nullptr};
    if (!e[i]) cudaEventCreateWithFlags(&e[i], cudaEventDisableTiming);
    return e[i];
}

// ---------------------------------------------------------------------------
// Launch DAG (R4 structure, full-grid scatters):
//   stream0: memset_i -> i2u x3 -> u2i x3 -> gemm_u -> join
//   s1:      memset_u -> (wait i2u) gemm_i [overlaps u2i tail]
// ---------------------------------------------------------------------------
extern "C" void kernel_launch(void* const* d_in, const int* in_sizes, int n_in,
                              void* d_out, int out_size)
{
    const float* user_emb = (const float*)d_in[0];
    const float* item_emb = (const float*)d_in[1];
    const float* u2i_vals = (const float*)d_in[2];
    const int*   u2i_rows = (const int*)  d_in[3];
    const int*   u2i_cols = (const int*)  d_in[4];
    const float* i2u_vals = (const float*)d_in[5];
    const int*   i2u_rows = (const int*)  d_in[6];
    const int*   i2u_cols = (const int*)  d_in[7];
    const float* u_w      = (const float*)d_in[8];
    const float* i_w      = (const float*)d_in[9];

    float* out     = (float*)d_out;
    float* out_ue  = out;                                                 // [NU,64]
    float* out_ie  = out + (size_t)NU * DD;                               // [NI,64]
    float* out_ues = out + (size_t)(NU + NI) * DD;                        // [3,NU,64]
    float* out_ies = out + (size_t)(NU + NI) * DD + (size_t)BB * NU * DD; // [3,NI,64]

    void* p;
    cudaGetSymbolAddress(&p, g_uscr); float* uscr = (float*)p;
    cudaGetSymbolAddress(&p, g_iscr); float* iscr = (float*)p;

    cudaStream_t s1 = side_stream();
    cudaEvent_t e_fork = ev(0), e_mu = ev(1), e_i2u = ev(2), e_join = ev(3);

    cudaEventRecord(e_fork, 0);
    cudaStreamWaitEvent(s1, e_fork, 0);

    cudaMemsetAsync(uscr, 0, sizeof(g_uscr), s1);
    cudaEventRecord(e_mu, s1);

    cudaMemsetAsync(iscr, 0, sizeof(g_iscr), 0);

    const int FULL_GRID = (EE + 255) / 256;

    for (int b = 0; b < BB; b++) {
        scatter_kernel<<<FULL_GRID, 256>>>(
            i2u_vals + (size_t)b * EE, i2u_rows + (size_t)b * EE,
            i2u_cols + (size_t)b * EE, user_emb,
            iscr + (size_t)b * NI * DD, EE);
    }
    cudaEventRecord(e_i2u, 0);

    // s1: item GEMM (tensor-core), overlaps the u2i scatters below
    cudaStreamWaitEvent(s1, e_i2u, 0);
    gemm_sig_mma<<<(NI + 63) / 64, 256, 0, s1>>>(iscr, i_w, out_ies, out_ie, NI);
    cudaEventRecord(e_join, s1);

    cudaStreamWaitEvent(0, e_mu, 0);
    for (int b = 0; b < BB; b++) {
        scatter_kernel<<<FULL_GRID, 256>>>(
            u2i_vals + (size_t)b * EE, u2i_rows + (size_t)b * EE,
            u2i_cols + (size_t)b * EE, item_emb,
            uscr + (size_t)b * NU * DD, EE);
    }
    gemm_sig_mma<<<(NU + 63) / 64, 256>>>(uscr, u_w, out_ues, out_ue, NU);

    cudaStreamWaitEvent(0, e_join, 0);
}

// round 7
// speedup vs baseline: 1.2281x; 1.1287x over previous
#include <cuda_runtime.h>
#include <cstdint>
#include <cstddef>

#define NU 100000
#define NI 200000
#define BB 3
#define EE 1000000
#define DD 64

// Scratch accumulators (device globals: allocation-free per harness rules)
__device__ float g_uscr[(size_t)BB * NU * DD];   // 76.8 MB
__device__ float g_iscr[(size_t)BB * NI * DD];   // 153.6 MB

// ---------------------------------------------------------------------------
// Scatter: COO spmm  out[row] += val * dense[col]  (red.global.add.v4.f32)
// Grid-stride persistent; at FULL_GRID it sweeps once (R1 config, 46.9us).
// ---------------------------------------------------------------------------
__global__ void __launch_bounds__(256) scatter_kernel(
    const float* __restrict__ vals,
    const int*   __restrict__ rows,
    const int*   __restrict__ cols,
    const float* __restrict__ dense,
    float*       __restrict__ out,
    int nE)
{
    int lane   = threadIdx.x & 31;
    int warpId = (blockIdx.x * blockDim.x + threadIdx.x) >> 5;
    int nWarps = (gridDim.x * blockDim.x) >> 5;
    int half   = lane >> 4;
    int l4     = lane & 15;

    for (int base = warpId * 32; base < nE; base += nWarps * 32) {
        int e = base + lane;
        float v = 0.0f; int r = 0, c = 0;
        if (e < nE) { v = vals[e]; r = rows[e]; c = cols[e]; }

        #pragma unroll
        for (int i = 0; i < 16; i++) {
            int src = 2 * i + half;
            float vv = __shfl_sync(0xffffffffu, v, src);
            int   rr = __shfl_sync(0xffffffffu, r, src);
            int   cc = __shfl_sync(0xffffffffu, c, src);

            const float4* dp = reinterpret_cast<const float4*>(dense + (size_t)cc * DD) + l4;
            float4 d = __ldg(dp);
            float4 p;
            p.x = vv * d.x; p.y = vv * d.y; p.z = vv * d.z; p.w = vv * d.w;

            float* op = out + (size_t)rr * DD + (size_t)l4 * 4;
            asm volatile("red.global.add.v4.f32 [%0], {%1,%2,%3,%4};"
                         :: "l"(op), "f"(p.x), "f"(p.y), "f"(p.z), "f"(p.w)
                         : "memory");
        }
    }
}

// ---------------------------------------------------------------------------
// tf32 tensor-core GEMM + sigmoid + in-register behavior mean, smem-staged.
// Block: 64 rows x 64 cols x 3 behaviors; 8 warps (4 m-tiles x 2 n-halves).
// X tile staged to smem with coalesced LDG.128 + one-time tf32 cvt;
// stride 68 words -> conflict-free LDS fragments ((4*gid+tig)%32 distinct).
// ---------------------------------------------------------------------------
__device__ __forceinline__ float sigmoidf_(float x) {
    return 1.0f / (1.0f + __expf(-x));
}
__device__ __forceinline__ uint32_t to_tf32(float x) {
    uint32_t v;
    asm("cvt.rna.tf32.f32 %0, %1;" : "=r"(v) : "f"(x));
    return v;
}
#define MMA_TF32(c0,c1,c2,c3, a0,a1,a2,a3, b0,b1)                            \
    asm volatile("mma.sync.aligned.m16n8k8.row.col.f32.tf32.tf32.f32 "       \
        "{%0,%1,%2,%3}, {%4,%5,%6,%7}, {%8,%9}, {%0,%1,%2,%3};"              \
        : "+f"(c0), "+f"(c1), "+f"(c2), "+f"(c3)                             \
        : "r"(a0), "r"(a1), "r"(a2), "r"(a3), "r"(b0), "r"(b1))

#define XSTRIDE 68

__global__ void __launch_bounds__(256) gemm_sig_mma(
    const float* __restrict__ scr,      // [3, N, 64]
    const float* __restrict__ W,        // [64, 64] row-major (k, n)
    float*       __restrict__ out_per,  // [3, N, 64]
    float*       __restrict__ out_mean, // [N, 64]
    int N)
{
    __shared__ uint32_t sW[64 * 72];            // tf32 W, padded stride 72 (18 KB)
    __shared__ uint32_t sX[3 * 64 * XSTRIDE];   // tf32 X tile, stride 68 (52.2 KB)

    int t  = threadIdx.x;
    int n0 = blockIdx.x * 64;

    // Stage W (tf32)
    #pragma unroll
    for (int i = 0; i < 16; i++) {
        int j = t + i * 256;            // 0..4095
        sW[(j >> 6) * 72 + (j & 63)] = to_tf32(W[j]);
    }

    // Stage X: 3*64 rows x 16 float4 = 3072 float4, 12 per thread, coalesced
    const float4* scr4 = reinterpret_cast<const float4*>(scr);
    #pragma unroll
    for (int i = 0; i < 12; i++) {
        int u  = t + i * 256;           // 0..3071
        int rb = u >> 4;                // 0..191
        int kq = u & 15;
        int b  = rb >> 6;
        int r  = rb & 63;
        float4 x = make_float4(0.f, 0.f, 0.f, 0.f);
        if (n0 + r < N)
            x = scr4[((size_t)b * N + n0 + r) * 16 + kq];
        uint4 xt;
        xt.x = to_tf32(x.x); xt.y = to_tf32(x.y);
        xt.z = to_tf32(x.z); xt.w = to_tf32(x.w);
        // word address (rb*68 + kq*4) is 4-word aligned -> uint4 store OK
        *reinterpret_cast<uint4*>(&sX[rb * XSTRIDE + kq * 4]) = xt;
    }
    __syncthreads();

    int warp = t >> 5, lane = t & 31;
    int gid = lane >> 2, tig = lane & 3;
    int mt = warp & 3, nh = warp >> 2;

    int r0l = mt * 16 + gid;            // local row of frag rows 0-7
    int r1l = r0l + 8;
    int r0  = n0 + r0l;
    int r1  = n0 + r1l;
    bool p0 = r0 < N, p1 = r1 < N;

    float acc[3][4][4];
    #pragma unroll
    for (int b = 0; b < 3; b++)
        #pragma unroll
        for (int nt = 0; nt < 4; nt++)
            #pragma unroll
            for (int q = 0; q < 4; q++) acc[b][nt][q] = 0.0f;

    #pragma unroll
    for (int ks = 0; ks < 8; ks++) {
        int k0 = ks * 8;
        uint32_t bf[4][2];
        #pragma unroll
        for (int nt = 0; nt < 4; nt++) {
            int col = nh * 32 + nt * 8 + gid;
            bf[nt][0] = sW[(k0 + tig) * 72 + col];
            bf[nt][1] = sW[(k0 + tig + 4) * 72 + col];
        }
        #pragma unroll
        for (int b = 0; b < 3; b++) {
            const uint32_t* xb = sX + b * 64 * XSTRIDE;
            uint32_t a0 = xb[r0l * XSTRIDE + k0 + tig];
            uint32_t a1 = xb[r1l * XSTRIDE + k0 + tig];
            uint32_t a2 = xb[r0l * XSTRIDE + k0 + tig + 4];
            uint32_t a3 = xb[r1l * XSTRIDE + k0 + tig + 4];
            #pragma unroll
            for (int nt = 0; nt < 4; nt++)
                MMA_TF32(acc[b][nt][0], acc[b][nt][1], acc[b][nt][2], acc[b][nt][3],
                         a0, a1, a2, a3, bf[nt][0], bf[nt][1]);
        }
    }

    // Epilogue: sigmoid per behavior + sigmoid(mean of pre-activations)
    const float third = 1.0f / 3.0f;
    #pragma unroll
    for (int nt = 0; nt < 4; nt++) {
        int c0 = nh * 32 + nt * 8 + 2 * tig;
        float m0 = 0.0f, m1 = 0.0f, m2 = 0.0f, m3 = 0.0f;
        #pragma unroll
        for (int b = 0; b < 3; b++) {
            float y0 = acc[b][nt][0], y1 = acc[b][nt][1];
            float y2 = acc[b][nt][2], y3 = acc[b][nt][3];
            m0 += y0; m1 += y1; m2 += y2; m3 += y3;
            if (p0) *reinterpret_cast<float2*>(out_per + ((size_t)b * N + r0) * 64 + c0)
                        = make_float2(sigmoidf_(y0), sigmoidf_(y1));
            if (p1) *reinterpret_cast<float2*>(out_per + ((size_t)b * N + r1) * 64 + c0)
                        = make_float2(sigmoidf_(y2), sigmoidf_(y3));
        }
        if (p0) *reinterpret_cast<float2*>(out_mean + (size_t)r0 * 64 + c0)
                    = make_float2(sigmoidf_(m0 * third), sigmoidf_(m1 * third));
        if (p1) *reinterpret_cast<float2*>(out_mean + (size_t)r1 * 64 + c0)
                    = make_float2(sigmoidf_(m2 * third), sigmoidf_(m3 * third));
    }
}

// ---------------------------------------------------------------------------
// Lazy stream/event creation (first call = correctness run, outside capture).
// ---------------------------------------------------------------------------
static cudaStream_t side_stream() {
    static cudaStream_t s = nullptr;
    if (!s) cudaStreamCreateWithFlags(&s, cudaStreamNonBlocking);
    return s;
}
static cudaEvent_t ev(int i) {
    static cudaEvent_t e[4] = {nullptr, nullptr, nullptr, nullptr};
    if (!e[i]) cudaEventCreateWithFlags(&e[i], cudaEventDisableTiming);
    return e[i];
}

// ---------------------------------------------------------------------------
// Launch DAG (R4 structure, full-grid scatters):
//   stream0: memset_i -> i2u x3 -> u2i x3 -> gemm_u -> join
//   s1:      memset_u -> (wait i2u) gemm_i [overlaps u2i tail]
// ---------------------------------------------------------------------------
extern "C" void kernel_launch(void* const* d_in, const int* in_sizes, int n_in,
                              void* d_out, int out_size)
{
    const float* user_emb = (const float*)d_in[0];
    const float* item_emb = (const float*)d_in[1];
    const float* u2i_vals = (const float*)d_in[2];
    const int*   u2i_rows = (const int*)  d_in[3];
    const int*   u2i_cols = (const int*)  d_in[4];
    const float* i2u_vals = (const float*)d_in[5];
    const int*   i2u_rows = (const int*)  d_in[6];
    const int*   i2u_cols = (const int*)  d_in[7];
    const float* u_w      = (const float*)d_in[8];
    const float* i_w      = (const float*)d_in[9];

    float* out     = (float*)d_out;
    float* out_ue  = out;                                                 // [NU,64]
    float* out_ie  = out + (size_t)NU * DD;                               // [NI,64]
    float* out_ues = out + (size_t)(NU + NI) * DD;                        // [3,NU,64]
    float* out_ies = out + (size_t)(NU + NI) * DD + (size_t)BB * NU * DD; // [3,NI,64]

    void* p;
    cudaGetSymbolAddress(&p, g_uscr); float* uscr = (float*)p;
    cudaGetSymbolAddress(&p, g_iscr); float* iscr = (float*)p;

    cudaStream_t s1 = side_stream();
    cudaEvent_t e_fork = ev(0), e_mu = ev(1), e_i2u = ev(2), e_join = ev(3);

    cudaEventRecord(e_fork, 0);
    cudaStreamWaitEvent(s1, e_fork, 0);

    cudaMemsetAsync(uscr, 0, sizeof(g_uscr), s1);
    cudaEventRecord(e_mu, s1);

    cudaMemsetAsync(iscr, 0, sizeof(g_iscr), 0);

    const int FULL_GRID = (EE + 255) / 256;

    for (int b = 0; b < BB; b++) {
        scatter_kernel<<<FULL_GRID, 256>>>(
            i2u_vals + (size_t)b * EE, i2u_rows + (size_t)b * EE,
            i2u_cols + (size_t)b * EE, user_emb,
            iscr + (size_t)b * NI * DD, EE);
    }
    cudaEventRecord(e_i2u, 0);

    // s1: item GEMM (tensor-core), overlaps the u2i scatters below
    cudaStreamWaitEvent(s1, e_i2u, 0);
    gemm_sig_mma<<<(NI + 63) / 64, 256, 0, s1>>>(iscr, i_w, out_ies, out_ie, NI);
    cudaEventRecord(e_join, s1);

    cudaStreamWaitEvent(0, e_mu, 0);
    for (int b = 0; b < BB; b++) {
        scatter_kernel<<<FULL_GRID, 256>>>(
            u2i_vals + (size_t)b * EE, u2i_rows + (size_t)b * EE,
            u2i_cols + (size_t)b * EE, item_emb,
            uscr + (size_t)b * NU * DD, EE);
    }
    gemm_sig_mma<<<(NU + 63) / 64, 256>>>(uscr, u_w, out_ues, out_ue, NU);

    cudaStreamWaitEvent(0, e_join, 0);
}